// round 4
// baseline (speedup 1.0000x reference)
#include <cuda_runtime.h>
#include <cuda_bf16.h>

#define B_     16
#define N_     2048
#define NCTX   2047          // n_ctx = N - NQ
#define NSPLIT 16
#define OFFOUT (16LL*2048*64)

typedef unsigned long long ull;

// scratch: per-batch partial Gram matrices C (96x32) per split, and P^T (32x64)
__device__ float g_C[B_ * NSPLIT * 96 * 32];
__device__ float g_P[B_ * 32 * 64];

__device__ __forceinline__ void ffma2(ull& d, ull a, ull b) {
    asm("fma.rn.f32x2 %0, %1, %2, %0;" : "+l"(d) : "l"(a), "l"(b));
}
__device__ __forceinline__ float hsum2(ull v) {
    return __uint_as_float((unsigned)v) + __uint_as_float((unsigned)(v >> 32));
}
__device__ __forceinline__ ull dup2(float f) {
    unsigned u = __float_as_uint(f);
    return (ull)u | ((ull)u << 32);
}

// ---------------------------------------------------------------------------
// Kernel A: per (batch, split) partial C = X96[:, kv] @ Q_kv^T   (96 x 32)
// Register-tiled FFMA2 GEMM. Block = 128 thr, covers 128 n in one stage.
// Thread tile: 6 rows (rg=tid&15) x 4 q (qg=tid>>4). Packed over n-pairs.
// tile layout [96][130] floats (stride 130 words, 65 ull); per-lane n-stagger
// (pp+rg)&63 makes row-load banks 14*rg mod 32 -> all distinct.
// ---------------------------------------------------------------------------
__global__ void __launch_bounds__(128) kA(const float* __restrict__ x) {
    extern __shared__ float tile[];    // 96*130 floats = 49920 B
    const int s = blockIdx.x, b = blockIdx.y;
    const int tid = threadIdx.x;
    const int rg = tid & 15;           // 16 row groups * 6 rows
    const int qg = tid >> 4;           // 8 q groups * 4 q
    const float* xb = x + (size_t)b * 160 * N_;
    const int n0 = s * 128;

    // stage 96x128 tile (zero column n >= NCTX)
#pragma unroll
    for (int i = 0; i < 24; i++) {
        const int fi = tid + i * 128;
        const int r = fi >> 5, c4 = fi & 31;
        const int n = n0 + c4 * 4;
        float4 v = *reinterpret_cast<const float4*>(&xb[r * N_ + n]);
        if (n + 4 > NCTX) {
            if (n + 0 >= NCTX) v.x = 0.f;
            if (n + 1 >= NCTX) v.y = 0.f;
            if (n + 2 >= NCTX) v.z = 0.f;
            if (n + 3 >= NCTX) v.w = 0.f;
        }
        const int base = r * 130 + c4 * 4;
        tile[base + 0] = v.x; tile[base + 1] = v.y;
        tile[base + 2] = v.z; tile[base + 3] = v.w;
    }
    __syncthreads();

    const ull* tu = reinterpret_cast<const ull*>(tile);  // row stride 65 ull

    ull acc[6][4];
#pragma unroll
    for (int k = 0; k < 6; k++)
#pragma unroll
        for (int j = 0; j < 4; j++) acc[k][j] = 0ull;

    const int rbase = rg * 6;
    const int qbase = qg * 4;
#pragma unroll 2
    for (int pp = 0; pp < 64; pp++) {
        const int nu = (pp + rg) & 63;                 // staggered n-pair slot
        ull qv[4];
#pragma unroll
        for (int j = 0; j < 4; j++) qv[j] = tu[(qbase + j) * 65 + nu];
#pragma unroll
        for (int k = 0; k < 6; k++) {
            const ull rv = tu[(rbase + k) * 65 + nu];
#pragma unroll
            for (int j = 0; j < 4; j++) ffma2(acc[k][j], rv, qv[j]);
        }
    }

    float* outp = g_C + (size_t)(b * NSPLIT + s) * 3072;
#pragma unroll
    for (int k = 0; k < 6; k++)
#pragma unroll
        for (int j = 0; j < 4; j++)
            outp[(rbase + k) * 32 + qbase + j] = hsum2(acc[k][j]);
}

// ---------------------------------------------------------------------------
// Kernel B: per batch, reduce partial C, then the closed-form 3-layer recursion
// (unchanged from previous round — tiny cost)
// ---------------------------------------------------------------------------
__global__ void __launch_bounds__(256) kB(const float* __restrict__ alpha,
                                          const float* __restrict__ kpp,
                                          const float* __restrict__ emb,
                                          const float* __restrict__ M) {
    __shared__ float sC[3072];
    __shared__ float sS[2048];
    __shared__ float sW[64 * 33];
    __shared__ float sY[2048];
    __shared__ float sWs[2048];
    const int b = blockIdx.x, tid = threadIdx.x;

    for (int idx = tid; idx < 3072; idx += 256) {
        float v = 0.f;
        const float* p = g_C + (size_t)b * (NSPLIT * 3072) + idx;
#pragma unroll
        for (int sp = 0; sp < NSPLIT; sp++) v += p[sp * 3072];
        sC[idx] = v;
    }
    __syncthreads();

    const int i = tid >> 2;
    const int j0 = (tid & 3) * 8;
    float acc[8];

#pragma unroll
    for (int u = 0; u < 8; u++) acc[u] = 0.f;
    for (int k = 0; k < 64; k++) {
        const float ev = emb[i * 64 + k];
        const float* row = &sC[(32 + k) * 32 + j0];
#pragma unroll
        for (int u = 0; u < 8; u++) acc[u] += ev * row[u];
    }
#pragma unroll
    for (int u = 0; u < 8; u++) { sS[i * 32 + j0 + u] = acc[u]; sWs[i * 32 + j0 + u] = 0.f; }
    __syncthreads();

    const float c = kpp[0] / (float)NCTX;

    for (int l = 0; l < 3; l++) {
        const float al = alpha[l * 64 + i];
#pragma unroll
        for (int u = 0; u < 8; u++) {
            const float w = al * sS[i * 32 + j0 + u];
            sW[i * 33 + j0 + u] = w;
            sWs[i * 32 + j0 + u] += w;
        }
        __syncthreads();
#pragma unroll
        for (int u = 0; u < 8; u++) acc[u] = 0.f;
        for (int k = 0; k < 32; k++) {
            const float wv = sW[i * 33 + k];
            const float* g = &sC[k * 32 + j0];
#pragma unroll
            for (int u = 0; u < 8; u++) acc[u] += wv * g[u];
        }
#pragma unroll
        for (int u = 0; u < 8; u++) sY[i * 32 + j0 + u] = acc[u];
        __syncthreads();
#pragma unroll
        for (int u = 0; u < 8; u++) acc[u] = 0.f;
        for (int k = 0; k < 64; k++) {
            const float mv = M[i * 64 + k];
            const float* y = &sY[k * 32 + j0];
#pragma unroll
            for (int u = 0; u < 8; u++) acc[u] += mv * y[u];
        }
#pragma unroll
        for (int u = 0; u < 8; u++) sS[i * 32 + j0 + u] += c * acc[u];
        __syncthreads();
    }

    const int cc = i;
#pragma unroll
    for (int u = 0; u < 8; u++) acc[u] = 0.f;
    for (int d = 0; d < 64; d++) {
        const float ev = emb[d * 64 + cc];
        const float* wr = &sWs[d * 32 + j0];
#pragma unroll
        for (int u = 0; u < 8; u++) acc[u] += ev * wr[u];
    }
#pragma unroll
    for (int u = 0; u < 8; u++)
        g_P[(size_t)b * 2048 + (j0 + u) * 64 + cc] = c * acc[u];
}

// ---------------------------------------------------------------------------
// Kernel C: logits[b,n,:] = R^T h96[:,n] with R[k][c] = [Emb ; P^T] (96x64),
// softmax -> predictions. Register-tiled FFMA2 GEMM packed over c-pairs:
// R b64 loads give natural (c,c+1) pairs; v is stored DUPLICATED (both packed
// halves equal) at staging so the inner loop has zero pack instructions.
// Block = 128 thr, covers 64 n. Thread: 8 c (cg=tid&7) x 4 n (ng=tid>>3).
// Per-lane k-stagger (t+cg)%96 -> R-load banks 10*cg mod 32 all distinct.
// smem: sR [96][66] floats (25344 B) + sV [96][65] ull (49920 B) = 75264 B.
// ---------------------------------------------------------------------------
__global__ void __launch_bounds__(128) kC(const float* __restrict__ x,
                                          const float* __restrict__ emb,
                                          float* __restrict__ out) {
    extern __shared__ float sm[];
    float* sR = sm;                                        // 96*66 floats
    ull*   sV = reinterpret_cast<ull*>(sm + 96 * 66);      // 96*65 ull (8B aligned: 6336*4=25344)
    const int pb = blockIdx.x, b = blockIdx.y;
    const int tid = threadIdx.x;
    const int cg = tid & 7;            // 8 c-groups * 8 c
    const int ng = tid >> 3;           // 16 n-groups * 4 n
    const int n0 = pb * 64;
    const float* xb = x + (size_t)b * 160 * N_;

    // stage R: rows 0..63 <- Emb (f0 part), rows 64..95 <- P^T (q part)
#pragma unroll
    for (int i = 0; i < 48; i++) {
        const int fi = tid + i * 128;
        const int k = fi >> 6, cc = fi & 63;
        const float v = (k < 64) ? emb[k * 64 + cc]
                                 : g_P[(size_t)b * 2048 + (k - 64) * 64 + cc];
        sR[k * 66 + cc] = v;
    }
    // stage v duplicated: rows 0..63 <- x rows 96..159 (F), rows 64..95 <- x rows 0..31 (Q)
#pragma unroll
    for (int i = 0; i < 12; i++) {
        const int fi = tid + i * 128;
        const int r = fi >> 4, c4 = fi & 15;
        const int xr = (r < 64) ? (96 + r) : (r - 64);
        const float4 v = *reinterpret_cast<const float4*>(&xb[xr * N_ + n0 + c4 * 4]);
        ull* dst = &sV[r * 65 + c4 * 4];
        dst[0] = dup2(v.x); dst[1] = dup2(v.y);
        dst[2] = dup2(v.z); dst[3] = dup2(v.w);
    }
    __syncthreads();

    ull acc[4][4];                     // [c-pair][n]
#pragma unroll
    for (int jp = 0; jp < 4; jp++)
#pragma unroll
        for (int ns = 0; ns < 4; ns++) acc[jp][ns] = 0ull;

    const ull* sRu = reinterpret_cast<const ull*>(sR);
    const int vbase = ng * 4;
    const int rbase = cg * 4;
#pragma unroll 2
    for (int t = 0; t < 96; t++) {
        int kk = t + cg; if (kk >= 96) kk -= 96;   // lane-staggered k
        ull vv[4];
        const ull* vp = &sV[kk * 65 + vbase];
#pragma unroll
        for (int ns = 0; ns < 4; ns++) vv[ns] = vp[ns];
        const ull* rp = sRu + 33 * kk + rbase;     // word offset 66*kk (even) + 8*cg
#pragma unroll
        for (int jp = 0; jp < 4; jp++) {
            const ull rv = rp[jp];
#pragma unroll
            for (int ns = 0; ns < 4; ns++) ffma2(acc[jp][ns], rv, vv[ns]);
        }
    }

    // softmax over 64 c per n (8 local + reduce across 8 cg lanes) + stores
#pragma unroll
    for (int ns = 0; ns < 4; ns++) {
        float vals[8];
#pragma unroll
        for (int jp = 0; jp < 4; jp++) {
            vals[2 * jp]     = __uint_as_float((unsigned)acc[jp][ns]);
            vals[2 * jp + 1] = __uint_as_float((unsigned)(acc[jp][ns] >> 32));
        }
        float m = vals[0];
#pragma unroll
        for (int u = 1; u < 8; u++) m = fmaxf(m, vals[u]);
#pragma unroll
        for (int o = 1; o < 8; o <<= 1) m = fmaxf(m, __shfl_xor_sync(0xffffffffu, m, o));
        float e[8]; float su = 0.f;
#pragma unroll
        for (int u = 0; u < 8; u++) { e[u] = __expf(vals[u] - m); su += e[u]; }
#pragma unroll
        for (int o = 1; o < 8; o <<= 1) su += __shfl_xor_sync(0xffffffffu, su, o);
        const float inv = 1.f / su;

        const int n = n0 + vbase + ns;
        const size_t base = ((size_t)b * N_ + n) * 64 + cg * 8;
        *reinterpret_cast<float4*>(&out[base])     = make_float4(vals[0], vals[1], vals[2], vals[3]);
        *reinterpret_cast<float4*>(&out[base + 4]) = make_float4(vals[4], vals[5], vals[6], vals[7]);
        *reinterpret_cast<float4*>(&out[OFFOUT + base]) =
            make_float4(e[0] * inv, e[1] * inv, e[2] * inv, e[3] * inv);
        *reinterpret_cast<float4*>(&out[OFFOUT + base + 4]) =
            make_float4(e[4] * inv, e[5] * inv, e[6] * inv, e[7] * inv);
    }
}

extern "C" void kernel_launch(void* const* d_in, const int* in_sizes, int n_in,
                              void* d_out, int out_size) {
    const float* x     = (const float*)d_in[0];
    const float* alpha = (const float*)d_in[1];
    const float* kp    = (const float*)d_in[2];
    const float* emb   = (const float*)d_in[3];
    const float* M     = (const float*)d_in[4];
    float* out = (float*)d_out;

    const int kaSmem = 96 * 130 * 4;            // 49920
    const int kcSmem = 96 * 66 * 4 + 96 * 65 * 8;  // 25344 + 49920 = 75264
    cudaFuncSetAttribute(kA, cudaFuncAttributeMaxDynamicSharedMemorySize, kaSmem);
    cudaFuncSetAttribute(kC, cudaFuncAttributeMaxDynamicSharedMemorySize, kcSmem);

    kA<<<dim3(NSPLIT, B_), 128, kaSmem>>>(x);
    kB<<<B_, 256>>>(alpha, kp, emb, M);
    kC<<<dim3(N_ / 64, B_), 128, kcSmem>>>(x, emb, out);
}

// round 5
// speedup vs baseline: 1.1795x; 1.1795x over previous
#include <cuda_runtime.h>
#include <cuda_bf16.h>

#define B_     16
#define N_     2048
#define NCTX   2047          // n_ctx = N - NQ
#define NSPLIT 32
#define OFFOUT (16LL*2048*64)

typedef unsigned long long ull;

// scratch: per-batch partial Gram matrices C (96x32) per split, and P^T (32x64)
__device__ float g_C[B_ * NSPLIT * 96 * 32];
__device__ float g_P[B_ * 32 * 64];

__device__ __forceinline__ void ffma2(ull& d, ull a, ull b) {
    asm("fma.rn.f32x2 %0, %1, %2, %0;" : "+l"(d) : "l"(a), "l"(b));
}
__device__ __forceinline__ float hsum2(ull v) {
    return __uint_as_float((unsigned)v) + __uint_as_float((unsigned)(v >> 32));
}
__device__ __forceinline__ ull dup2(float f) {
    unsigned u = __float_as_uint(f);
    return (ull)u | ((ull)u << 32);
}

// ---------------------------------------------------------------------------
// Kernel A: per (batch, split) partial C = X96[:, kv] @ Q_kv^T   (96 x 32)
// 64-n tiles (NSPLIT=32) for residency: smem 25.3KB -> ~3.5 blocks/SM, all
// 512 blocks co-resident. Thread tile 6 rows x 4 q, FFMA2 over n-pairs.
// tile: [96][66] floats = [96][33] ull. Row-load banks 7*rg mod 16 distinct.
// ---------------------------------------------------------------------------
__global__ void __launch_bounds__(128) kA(const float* __restrict__ x) {
    extern __shared__ float tile[];    // 96*66 floats = 25344 B
    const int s = blockIdx.x, b = blockIdx.y;
    const int tid = threadIdx.x;
    const int rg = tid & 15;           // 16 row groups * 6 rows
    const int qg = tid >> 4;           // 8 q groups * 4 q
    const float* xb = x + (size_t)b * 160 * N_;
    const int n0 = s * 64;

    // stage 96x64 tile (zero column n >= NCTX)
#pragma unroll
    for (int i = 0; i < 12; i++) {
        const int fi = tid + i * 128;
        const int r = fi >> 4, c4 = fi & 15;
        const int n = n0 + c4 * 4;
        float4 v = *reinterpret_cast<const float4*>(&xb[r * N_ + n]);
        if (n + 4 > NCTX) {
            if (n + 0 >= NCTX) v.x = 0.f;
            if (n + 1 >= NCTX) v.y = 0.f;
            if (n + 2 >= NCTX) v.z = 0.f;
            if (n + 3 >= NCTX) v.w = 0.f;
        }
        const int base = r * 66 + c4 * 4;
        tile[base + 0] = v.x; tile[base + 1] = v.y;
        tile[base + 2] = v.z; tile[base + 3] = v.w;
    }
    __syncthreads();

    const ull* tu = reinterpret_cast<const ull*>(tile);  // row stride 33 ull

    ull acc[6][4];
#pragma unroll
    for (int k = 0; k < 6; k++)
#pragma unroll
        for (int j = 0; j < 4; j++) acc[k][j] = 0ull;

    const int rbase = rg * 6;
    const int qbase = qg * 4;
#pragma unroll 2
    for (int pp = 0; pp < 32; pp++) {
        const int nu = (pp + rg) & 31;                 // staggered n-pair slot
        ull qv[4];
#pragma unroll
        for (int j = 0; j < 4; j++) qv[j] = tu[(qbase + j) * 33 + nu];
#pragma unroll
        for (int k = 0; k < 6; k++) {
            const ull rv = tu[(rbase + k) * 33 + nu];
#pragma unroll
            for (int j = 0; j < 4; j++) ffma2(acc[k][j], rv, qv[j]);
        }
    }

    float* outp = g_C + (size_t)(b * NSPLIT + s) * 3072;
#pragma unroll
    for (int k = 0; k < 6; k++) {
        float4 o = make_float4(hsum2(acc[k][0]), hsum2(acc[k][1]),
                               hsum2(acc[k][2]), hsum2(acc[k][3]));
        *reinterpret_cast<float4*>(&outp[(rbase + k) * 32 + qbase]) = o;
    }
}

// ---------------------------------------------------------------------------
// Kernel B: per batch, reduce partial C (float4, NSPLIT=32), then the
// closed-form 3-layer recursion. Tiny cost.
// ---------------------------------------------------------------------------
__global__ void __launch_bounds__(256) kB(const float* __restrict__ alpha,
                                          const float* __restrict__ kpp,
                                          const float* __restrict__ emb,
                                          const float* __restrict__ M) {
    __shared__ float sC[3072];
    __shared__ float sS[2048];
    __shared__ float sW[64 * 33];
    __shared__ float sY[2048];
    __shared__ float sWs[2048];
    const int b = blockIdx.x, tid = threadIdx.x;

    // reduce: 768 float4 slots, 3 per thread, 32 partials each
    const float4* gc = reinterpret_cast<const float4*>(g_C + (size_t)b * (NSPLIT * 3072));
#pragma unroll
    for (int i = 0; i < 3; i++) {
        const int idx4 = tid + i * 256;
        float4 a = make_float4(0.f, 0.f, 0.f, 0.f);
#pragma unroll
        for (int sp = 0; sp < NSPLIT; sp++) {
            const float4 v = gc[sp * 768 + idx4];
            a.x += v.x; a.y += v.y; a.z += v.z; a.w += v.w;
        }
        *reinterpret_cast<float4*>(&sC[idx4 * 4]) = a;
    }
    __syncthreads();

    const int i = tid >> 2;
    const int j0 = (tid & 3) * 8;
    float acc[8];

#pragma unroll
    for (int u = 0; u < 8; u++) acc[u] = 0.f;
    for (int k = 0; k < 64; k++) {
        const float ev = emb[i * 64 + k];
        const float* row = &sC[(32 + k) * 32 + j0];
#pragma unroll
        for (int u = 0; u < 8; u++) acc[u] += ev * row[u];
    }
#pragma unroll
    for (int u = 0; u < 8; u++) { sS[i * 32 + j0 + u] = acc[u]; sWs[i * 32 + j0 + u] = 0.f; }
    __syncthreads();

    const float c = kpp[0] / (float)NCTX;

    for (int l = 0; l < 3; l++) {
        const float al = alpha[l * 64 + i];
#pragma unroll
        for (int u = 0; u < 8; u++) {
            const float w = al * sS[i * 32 + j0 + u];
            sW[i * 33 + j0 + u] = w;
            sWs[i * 32 + j0 + u] += w;
        }
        __syncthreads();
#pragma unroll
        for (int u = 0; u < 8; u++) acc[u] = 0.f;
        for (int k = 0; k < 32; k++) {
            const float wv = sW[i * 33 + k];
            const float* g = &sC[k * 32 + j0];
#pragma unroll
            for (int u = 0; u < 8; u++) acc[u] += wv * g[u];
        }
#pragma unroll
        for (int u = 0; u < 8; u++) sY[i * 32 + j0 + u] = acc[u];
        __syncthreads();
#pragma unroll
        for (int u = 0; u < 8; u++) acc[u] = 0.f;
        for (int k = 0; k < 64; k++) {
            const float mv = M[i * 64 + k];
            const float* y = &sY[k * 32 + j0];
#pragma unroll
            for (int u = 0; u < 8; u++) acc[u] += mv * y[u];
        }
#pragma unroll
        for (int u = 0; u < 8; u++) sS[i * 32 + j0 + u] += c * acc[u];
        __syncthreads();
    }

    const int cc = i;
#pragma unroll
    for (int u = 0; u < 8; u++) acc[u] = 0.f;
    for (int d = 0; d < 64; d++) {
        const float ev = emb[d * 64 + cc];
        const float* wr = &sWs[d * 32 + j0];
#pragma unroll
        for (int u = 0; u < 8; u++) acc[u] += ev * wr[u];
    }
#pragma unroll
    for (int u = 0; u < 8; u++)
        g_P[(size_t)b * 2048 + (j0 + u) * 64 + cc] = c * acc[u];
}

// ---------------------------------------------------------------------------
// Kernel C: logits[b,n,:] = R^T h96[:,n] with R[k][c] = [Emb ; P^T] (96x64),
// softmax -> predictions.
// R stored c-major, read as ld.shared.v2.u64 -> natural c-pairs, ZERO packs.
// v read as float4 (uniform row per warp -> broadcast), dup'd in registers
// (8 MOV per iter vs 16 FFMA2). smem 52.2KB -> 4 blocks/SM, grid 512 resident.
// Block = 128 thr / 64 n. Thread: 8 c (cg=tid&7) x 4 n (ng=tid>>3).
// ---------------------------------------------------------------------------
__global__ void __launch_bounds__(128) kC(const float* __restrict__ x,
                                          const float* __restrict__ emb,
                                          float* __restrict__ out) {
    extern __shared__ float sm[];
    float* sR = sm;                   // [96][68] floats = 26112 B
    float* sV = sm + 96 * 68;         // [96][68] floats = 26112 B
    const int pb = blockIdx.x, b = blockIdx.y;
    const int tid = threadIdx.x;
    const int cg = tid & 7;            // 8 c-groups * 8 c
    const int ng = tid >> 3;           // 16 n-groups * 4 n
    const int n0 = pb * 64;
    const float* xb = x + (size_t)b * 160 * N_;

    // stage R: rows 0..63 <- Emb, rows 64..95 <- P^T
#pragma unroll
    for (int i = 0; i < 48; i++) {
        const int fi = tid + i * 128;
        const int k = fi >> 6, cc = fi & 63;
        const float v = (k < 64) ? emb[fi]
                                 : g_P[(size_t)b * 2048 + fi - 4096];
        sR[k * 68 + cc] = v;
    }
    // stage v: rows 0..63 <- x rows 96..159 (F), rows 64..95 <- x rows 0..31 (Q)
#pragma unroll
    for (int i = 0; i < 12; i++) {
        const int fi = tid + i * 128;
        const int r = fi >> 4, c4 = fi & 15;
        const int xr = (r < 64) ? (96 + r) : (r - 64);
        const float4 v = *reinterpret_cast<const float4*>(&xb[xr * N_ + n0 + c4 * 4]);
        const int base = r * 68 + c4 * 4;
        sV[base + 0] = v.x; sV[base + 1] = v.y;
        sV[base + 2] = v.z; sV[base + 3] = v.w;
    }
    __syncthreads();

    ull acc[4][4];                     // [c-pair][n]
#pragma unroll
    for (int jp = 0; jp < 4; jp++)
#pragma unroll
        for (int ns = 0; ns < 4; ns++) acc[jp][ns] = 0ull;

    const ulonglong2* sR2 = reinterpret_cast<const ulonglong2*>(sR);  // row stride 17
    const float4*     sV4 = reinterpret_cast<const float4*>(sV);      // row stride 17

#pragma unroll 2
    for (int t = 0; t < 96; t++) {
        const ulonglong2 r01 = sR2[t * 17 + cg * 2];      // c = cg*8 .. +3
        const ulonglong2 r23 = sR2[t * 17 + cg * 2 + 1];  // c = cg*8+4 .. +7
        const float4 vv = sV4[t * 17 + ng];               // n = ng*4 .. +3
        ull dv[4];
        dv[0] = dup2(vv.x); dv[1] = dup2(vv.y);
        dv[2] = dup2(vv.z); dv[3] = dup2(vv.w);
        ull rp[4] = { r01.x, r01.y, r23.x, r23.y };
#pragma unroll
        for (int jp = 0; jp < 4; jp++)
#pragma unroll
            for (int ns = 0; ns < 4; ns++) ffma2(acc[jp][ns], rp[jp], dv[ns]);
    }

    // softmax over 64 c per n (8 local + reduce across 8 cg lanes) + stores
#pragma unroll
    for (int ns = 0; ns < 4; ns++) {
        float vals[8];
#pragma unroll
        for (int jp = 0; jp < 4; jp++) {
            vals[2 * jp]     = __uint_as_float((unsigned)acc[jp][ns]);
            vals[2 * jp + 1] = __uint_as_float((unsigned)(acc[jp][ns] >> 32));
        }
        float m = vals[0];
#pragma unroll
        for (int u = 1; u < 8; u++) m = fmaxf(m, vals[u]);
#pragma unroll
        for (int o = 1; o < 8; o <<= 1) m = fmaxf(m, __shfl_xor_sync(0xffffffffu, m, o));
        float e[8]; float su = 0.f;
#pragma unroll
        for (int u = 0; u < 8; u++) { e[u] = __expf(vals[u] - m); su += e[u]; }
#pragma unroll
        for (int o = 1; o < 8; o <<= 1) su += __shfl_xor_sync(0xffffffffu, su, o);
        const float inv = 1.f / su;

        const int n = n0 + ng * 4 + ns;
        const size_t base = ((size_t)b * N_ + n) * 64 + cg * 8;
        *reinterpret_cast<float4*>(&out[base])     = make_float4(vals[0], vals[1], vals[2], vals[3]);
        *reinterpret_cast<float4*>(&out[base + 4]) = make_float4(vals[4], vals[5], vals[6], vals[7]);
        *reinterpret_cast<float4*>(&out[OFFOUT + base]) =
            make_float4(e[0] * inv, e[1] * inv, e[2] * inv, e[3] * inv);
        *reinterpret_cast<float4*>(&out[OFFOUT + base + 4]) =
            make_float4(e[4] * inv, e[5] * inv, e[6] * inv, e[7] * inv);
    }
}

extern "C" void kernel_launch(void* const* d_in, const int* in_sizes, int n_in,
                              void* d_out, int out_size) {
    const float* x     = (const float*)d_in[0];
    const float* alpha = (const float*)d_in[1];
    const float* kp    = (const float*)d_in[2];
    const float* emb   = (const float*)d_in[3];
    const float* M     = (const float*)d_in[4];
    float* out = (float*)d_out;

    const int kaSmem = 96 * 66 * 4;       // 25344
    const int kcSmem = 2 * 96 * 68 * 4;   // 52224
    cudaFuncSetAttribute(kA, cudaFuncAttributeMaxDynamicSharedMemorySize, kaSmem);
    cudaFuncSetAttribute(kC, cudaFuncAttributeMaxDynamicSharedMemorySize, kcSmem);

    kA<<<dim3(NSPLIT, B_), 128, kaSmem>>>(x);
    kB<<<B_, 256>>>(alpha, kp, emb, M);
    kC<<<dim3(N_ / 64, B_), 128, kcSmem>>>(x, emb, out);
}